// round 1
// baseline (speedup 1.0000x reference)
#include <cuda_runtime.h>
#include <cuda_bf16.h>
#include <math.h>

// Problem constants
#define BB 8
#define SS 1024
#define DD 1024
#define HH 16
#define DHD 64
#define MROWS (BB * SS) /* 8192 */

// Scratch: __device__ globals (no runtime allocation allowed)
__device__ float g_q[(size_t)BB * HH * SS * DHD];     // 32 MB  [B,H,S,DH]
__device__ float g_k[(size_t)BB * HH * SS * DHD];     // 32 MB
__device__ float g_v[(size_t)BB * HH * SS * DHD];     // 32 MB
__device__ float g_sc[(size_t)BB * HH * SS * SS];     // 512 MB [B,H,S,S]
__device__ float g_ctx[(size_t)BB * SS * DD];         // 32 MB  [B,S,D]

// ---------------------------------------------------------------------------
// Kernel 1: NT projection GEMM.  C[m,n] = sum_k X[m,k]*W[n,k] + bias[n], *scale
// X: [MROWS, DD] row-major, W: [DD, DD] row-major (both K-contiguous -> NT).
// Tile 128x128, K-step 8, 256 threads, 8x8 register micro-tile.
// scatter=1: write to [B,H,S,DH] layout (for q/k/v). scatter=0: plain [M,N].
// ---------------------------------------------------------------------------
__global__ __launch_bounds__(256) void proj_nt_kernel(
    const float* __restrict__ X, const float* __restrict__ W,
    const float* __restrict__ bias, float* __restrict__ out,
    float scale, int scatter)
{
    __shared__ float As[8][128];
    __shared__ float Bs[8][128];
    const int tid = threadIdx.x;
    const int bm = blockIdx.y * 128;
    const int bn = blockIdx.x * 128;
    const int tm = tid >> 4;        // 0..15
    const int tn = tid & 15;        // 0..15
    const int lr = tid >> 1;        // 0..127 (tile row to load)
    const int lc = (tid & 1) * 4;   // 0 or 4 (k offset to load)

    float acc[8][8];
#pragma unroll
    for (int i = 0; i < 8; i++)
#pragma unroll
        for (int j = 0; j < 8; j++) acc[i][j] = 0.0f;

    for (int k0 = 0; k0 < DD; k0 += 8) {
        float4 av = *(const float4*)(X + (size_t)(bm + lr) * DD + k0 + lc);
        float4 bv = *(const float4*)(W + (size_t)(bn + lr) * DD + k0 + lc);
        As[lc + 0][lr] = av.x; As[lc + 1][lr] = av.y;
        As[lc + 2][lr] = av.z; As[lc + 3][lr] = av.w;
        Bs[lc + 0][lr] = bv.x; Bs[lc + 1][lr] = bv.y;
        Bs[lc + 2][lr] = bv.z; Bs[lc + 3][lr] = bv.w;
        __syncthreads();
#pragma unroll
        for (int kk = 0; kk < 8; kk++) {
            float a[8], b[8];
            *(float4*)(a)     = *(const float4*)&As[kk][tm * 8];
            *(float4*)(a + 4) = *(const float4*)&As[kk][tm * 8 + 4];
            *(float4*)(b)     = *(const float4*)&Bs[kk][tn * 8];
            *(float4*)(b + 4) = *(const float4*)&Bs[kk][tn * 8 + 4];
#pragma unroll
            for (int i = 0; i < 8; i++)
#pragma unroll
                for (int j = 0; j < 8; j++) acc[i][j] += a[i] * b[j];
        }
        __syncthreads();
    }

#pragma unroll
    for (int i = 0; i < 8; i++) {
        const int m = bm + tm * 8 + i;
#pragma unroll
        for (int j = 0; j < 8; j++) {
            const int n = bn + tn * 8 + j;
            const float v = (acc[i][j] + bias[n]) * scale;
            if (scatter) {
                const int b = m >> 10;      // / SS
                const int s = m & 1023;     // % SS
                const int h = n >> 6;       // / DHD
                const int d = n & 63;       // % DHD
                out[((size_t)((b * HH + h) * SS + s)) * DHD + d] = v;
            } else {
                out[(size_t)m * DD + n] = v;
            }
        }
    }
}

// ---------------------------------------------------------------------------
// Kernel 2: scores (NT batched GEMM, K=DH=64) + mask.
// Sc[b,h,m,n] = mask[b,m,n] ? -1e18 : dot(q[b,h,m,:], k[b,h,n,:])
// mask read as 32-bit words: nonzero <=> True (works for int32 0/1 and f32 0/1).
// ---------------------------------------------------------------------------
__global__ __launch_bounds__(256) void scores_kernel(const int* __restrict__ mask)
{
    const int bh = blockIdx.z;
    const int b = bh >> 4;
    const float* Q  = g_q + (size_t)bh * SS * DHD;
    const float* Kp = g_k + (size_t)bh * SS * DHD;
    float* Sc = g_sc + (size_t)bh * SS * SS;

    __shared__ float As[8][128];
    __shared__ float Bs[8][128];
    const int tid = threadIdx.x;
    const int bm = blockIdx.y * 128;
    const int bn = blockIdx.x * 128;
    const int tm = tid >> 4;
    const int tn = tid & 15;
    const int lr = tid >> 1;
    const int lc = (tid & 1) * 4;

    float acc[8][8];
#pragma unroll
    for (int i = 0; i < 8; i++)
#pragma unroll
        for (int j = 0; j < 8; j++) acc[i][j] = 0.0f;

    for (int k0 = 0; k0 < DHD; k0 += 8) {
        float4 av = *(const float4*)(Q  + (size_t)(bm + lr) * DHD + k0 + lc);
        float4 bv = *(const float4*)(Kp + (size_t)(bn + lr) * DHD + k0 + lc);
        As[lc + 0][lr] = av.x; As[lc + 1][lr] = av.y;
        As[lc + 2][lr] = av.z; As[lc + 3][lr] = av.w;
        Bs[lc + 0][lr] = bv.x; Bs[lc + 1][lr] = bv.y;
        Bs[lc + 2][lr] = bv.z; Bs[lc + 3][lr] = bv.w;
        __syncthreads();
#pragma unroll
        for (int kk = 0; kk < 8; kk++) {
            float a[8], bfr[8];
            *(float4*)(a)       = *(const float4*)&As[kk][tm * 8];
            *(float4*)(a + 4)   = *(const float4*)&As[kk][tm * 8 + 4];
            *(float4*)(bfr)     = *(const float4*)&Bs[kk][tn * 8];
            *(float4*)(bfr + 4) = *(const float4*)&Bs[kk][tn * 8 + 4];
#pragma unroll
            for (int i = 0; i < 8; i++)
#pragma unroll
                for (int j = 0; j < 8; j++) acc[i][j] += a[i] * bfr[j];
        }
        __syncthreads();
    }

#pragma unroll
    for (int i = 0; i < 8; i++) {
        const int m = bm + tm * 8 + i;
#pragma unroll
        for (int j = 0; j < 8; j++) {
            const int n = bn + tn * 8 + j;
            const int msk = mask[(size_t)b * SS * SS + (size_t)m * SS + n];
            Sc[(size_t)m * SS + n] = msk ? -1e18f : acc[i][j];
        }
    }
}

// ---------------------------------------------------------------------------
// Kernel 3: row softmax (in-place on g_sc), plus last-head graph reweighting.
// One block (256 threads) per row; each thread owns 4 coalesced elements.
// ---------------------------------------------------------------------------
__device__ __forceinline__ float warp_max(float v) {
#pragma unroll
    for (int o = 16; o; o >>= 1) v = fmaxf(v, __shfl_xor_sync(0xffffffffu, v, o));
    return v;
}
__device__ __forceinline__ float warp_sum(float v) {
#pragma unroll
    for (int o = 16; o; o >>= 1) v += __shfl_xor_sync(0xffffffffu, v, o);
    return v;
}
__device__ __forceinline__ float block_max(float v, float* red) {
    const int lane = threadIdx.x & 31, wid = threadIdx.x >> 5;
    v = warp_max(v);
    if (lane == 0) red[wid] = v;
    __syncthreads();
    if (wid == 0) {
        float z = (lane < 8) ? red[lane] : -3.4e38f;
        z = warp_max(z);
        if (lane == 0) red[8] = z;
    }
    __syncthreads();
    const float r = red[8];
    __syncthreads();
    return r;
}
__device__ __forceinline__ float block_sum(float v, float* red) {
    const int lane = threadIdx.x & 31, wid = threadIdx.x >> 5;
    v = warp_sum(v);
    if (lane == 0) red[wid] = v;
    __syncthreads();
    if (wid == 0) {
        float z = (lane < 8) ? red[lane] : 0.0f;
        z = warp_sum(z);
        if (lane == 0) red[8] = z;
    }
    __syncthreads();
    const float r = red[8];
    __syncthreads();
    return r;
}

__global__ __launch_bounds__(256) void softmax_kernel(const float* __restrict__ graph)
{
    __shared__ float red[9];
    const int row = blockIdx.x;        // 0 .. B*H*S-1
    const int bh = row >> 10;
    const int m  = row & 1023;
    const int b  = bh >> 4;
    const int h  = bh & 15;
    float* Sc = g_sc + (size_t)row * SS;
    const int t = threadIdx.x;

    float x0 = Sc[t], x1 = Sc[t + 256], x2 = Sc[t + 512], x3 = Sc[t + 768];
    const float mx = block_max(fmaxf(fmaxf(x0, x1), fmaxf(x2, x3)), red);

    float e0 = __expf(x0 - mx), e1 = __expf(x1 - mx);
    float e2 = __expf(x2 - mx), e3 = __expf(x3 - mx);
    const float Z = block_sum(e0 + e1 + e2 + e3, red);
    const float inv = 1.0f / Z;
    float p0 = e0 * inv, p1 = e1 * inv, p2 = e2 * inv, p3 = e3 * inv;

    if (h == HH - 1) {
        const float* g = graph + (size_t)b * SS * SS + (size_t)m * SS;
        const float w0 = p0 * g[t],       w1 = p1 * g[t + 256];
        const float w2 = p2 * g[t + 512], w3 = p3 * g[t + 768];
        const float sw = block_sum(w0 + w1 + w2 + w3, red);
        const float invw = 1.0f / (sw + 1e-9f);
        p0 = w0 * invw; p1 = w1 * invw; p2 = w2 * invw; p3 = w3 * invw;
    }
    Sc[t] = p0; Sc[t + 256] = p1; Sc[t + 512] = p2; Sc[t + 768] = p3;
}

// ---------------------------------------------------------------------------
// Kernel 4: ctx = attn @ V  (NN batched GEMM, [1024x1024] @ [1024x64]).
// Tile M=128, N=64 (full), K-step 8.  Output written straight into the
// [B,S,D] layout consumed by the final projection.
// ---------------------------------------------------------------------------
__global__ __launch_bounds__(256) void ctx_kernel()
{
    const int bh = blockIdx.y;
    const int b = bh >> 4;
    const int h = bh & 15;
    const int bm = blockIdx.x * 128;
    const float* A = g_sc + (size_t)bh * SS * SS;
    const float* V = g_v  + (size_t)bh * SS * DHD;

    __shared__ float As[8][128];
    __shared__ float Bs[8][64];
    const int tid = threadIdx.x;
    const int tm = tid >> 4;       // 0..15 -> 8 m-rows each
    const int tn = tid & 15;       // 0..15 -> 4 n-cols each
    const int lr = tid >> 1;
    const int lc = (tid & 1) * 4;

    float acc[8][4];
#pragma unroll
    for (int i = 0; i < 8; i++)
#pragma unroll
        for (int j = 0; j < 4; j++) acc[i][j] = 0.0f;

    for (int k0 = 0; k0 < SS; k0 += 8) {
        float4 av = *(const float4*)(A + (size_t)(bm + lr) * SS + k0 + lc);
        As[lc + 0][lr] = av.x; As[lc + 1][lr] = av.y;
        As[lc + 2][lr] = av.z; As[lc + 3][lr] = av.w;
        if (tid < 128) {
            const int r = tid >> 4;           // 0..7 k-row
            const int c = (tid & 15) * 4;     // 0..60
            *(float4*)&Bs[r][c] = *(const float4*)(V + (size_t)(k0 + r) * DHD + c);
        }
        __syncthreads();
#pragma unroll
        for (int kk = 0; kk < 8; kk++) {
            float a[8], bfr[4];
            *(float4*)(a)     = *(const float4*)&As[kk][tm * 8];
            *(float4*)(a + 4) = *(const float4*)&As[kk][tm * 8 + 4];
            *(float4*)(bfr)   = *(const float4*)&Bs[kk][tn * 4];
#pragma unroll
            for (int i = 0; i < 8; i++)
#pragma unroll
                for (int j = 0; j < 4; j++) acc[i][j] += a[i] * bfr[j];
        }
        __syncthreads();
    }

#pragma unroll
    for (int i = 0; i < 8; i++) {
        const int m = bm + tm * 8 + i;
#pragma unroll
        for (int j = 0; j < 4; j++) {
            const int n = tn * 4 + j;
            g_ctx[((size_t)(b * SS + m)) * DD + h * DHD + n] = acc[i][j];
        }
    }
}

// ---------------------------------------------------------------------------
// Launch: 5 graph-capturable kernel launches, default stream ordering.
// Input order: key, value, query, mask, graph, Wq,bq, Wk,bk, Wv,bv, Wo,bo
// ---------------------------------------------------------------------------
extern "C" void kernel_launch(void* const* d_in, const int* in_sizes, int n_in,
                              void* d_out, int out_size)
{
    const float* key   = (const float*)d_in[0];
    const float* value = (const float*)d_in[1];
    const float* query = (const float*)d_in[2];
    const int*   mask  = (const int*)d_in[3];
    const float* graph = (const float*)d_in[4];
    const float* Wq = (const float*)d_in[5];  const float* bq = (const float*)d_in[6];
    const float* Wk = (const float*)d_in[7];  const float* bk = (const float*)d_in[8];
    const float* Wv = (const float*)d_in[9];  const float* bv = (const float*)d_in[10];
    const float* Wo = (const float*)d_in[11]; const float* bo = (const float*)d_in[12];
    float* out = (float*)d_out;

    float *qb, *kb, *vb, *ctxb;
    cudaGetSymbolAddress((void**)&qb,   g_q);
    cudaGetSymbolAddress((void**)&kb,   g_k);
    cudaGetSymbolAddress((void**)&vb,   g_v);
    cudaGetSymbolAddress((void**)&ctxb, g_ctx);

    const float qscale = 0.125f;  // 1/sqrt(64)

    dim3 projGrid(DD / 128, MROWS / 128);     // (8, 64)
    proj_nt_kernel<<<projGrid, 256>>>(query, Wq, bq, qb, qscale, 1);
    proj_nt_kernel<<<projGrid, 256>>>(key,   Wk, bk, kb, 1.0f,   1);
    proj_nt_kernel<<<projGrid, 256>>>(value, Wv, bv, vb, 1.0f,   1);

    dim3 scGrid(SS / 128, SS / 128, BB * HH); // (8, 8, 128)
    scores_kernel<<<scGrid, 256>>>(mask);

    softmax_kernel<<<BB * HH * SS, 256>>>(graph);

    dim3 ctxGrid(SS / 128, BB * HH);          // (8, 128)
    ctx_kernel<<<ctxGrid, 256>>>();

    proj_nt_kernel<<<projGrid, 256>>>(ctxb, Wo, bo, out, 1.0f, 0);
}

// round 13
// speedup vs baseline: 1.8570x; 1.8570x over previous
#include <cuda_runtime.h>
#include <cuda_bf16.h>
#include <cstdint>
#include <cstddef>

// Problem constants
#define BB 8
#define SS 1024
#define DD 1024
#define HH 16
#define DHD 64
#define MROWS (BB * SS) /* 8192 */

// ---------------------------------------------------------------------------
// Scratch (__device__ globals; no runtime allocation allowed)
// ---------------------------------------------------------------------------
__device__ float g_sc[(size_t)BB * HH * SS * SS];            // 512 MB [B,H,S,S]
__device__ float g_v [(size_t)BB * HH * SS * DHD];           // 32 MB  [B,H,S,DH]
__device__ float g_ctx[(size_t)BB * SS * DD];                // 32 MB  [B,S,D]
__device__ __nv_bfloat16 g_xh[(size_t)MROWS * DD];           // input split hi
__device__ __nv_bfloat16 g_xl[(size_t)MROWS * DD];           // input split lo
__device__ __nv_bfloat16 g_wh[(size_t)DD * DD];              // weight split hi
__device__ __nv_bfloat16 g_wl[(size_t)DD * DD];
__device__ __nv_bfloat16 g_qh[(size_t)BB * HH * SS * DHD];   // q hi [B,H,S,DH]
__device__ __nv_bfloat16 g_ql[(size_t)BB * HH * SS * DHD];
__device__ __nv_bfloat16 g_kh[(size_t)BB * HH * SS * DHD];
__device__ __nv_bfloat16 g_kl[(size_t)BB * HH * SS * DHD];

// ---------------------------------------------------------------------------
// HMMA m16n8k16 bf16 (standard PTX, valid on base sm_103 target)
// ---------------------------------------------------------------------------
__device__ __forceinline__ void mma16816(float* c, const uint32_t* a, const uint32_t* b) {
    asm volatile(
        "mma.sync.aligned.m16n8k16.row.col.f32.bf16.bf16.f32 "
        "{%0,%1,%2,%3},{%4,%5,%6,%7},{%8,%9},{%0,%1,%2,%3};"
        : "+f"(c[0]), "+f"(c[1]), "+f"(c[2]), "+f"(c[3])
        : "r"(a[0]), "r"(a[1]), "r"(a[2]), "r"(a[3]), "r"(b[0]), "r"(b[1]));
}

#define STA 40  /* padded SMEM row stride in bf16 (80 B: 16B-aligned, conflict-free) */

// ---------------------------------------------------------------------------
// split: fp32 -> bf16 hi/lo pair
// ---------------------------------------------------------------------------
__global__ __launch_bounds__(256) void split_kernel(
    const float4* __restrict__ src, __nv_bfloat162* __restrict__ hi,
    __nv_bfloat162* __restrict__ lo, int n4)
{
    int i = blockIdx.x * 256 + threadIdx.x;
    if (i >= n4) return;
    float4 v = src[i];
    __nv_bfloat16 h0 = __float2bfloat16(v.x), h1 = __float2bfloat16(v.y);
    __nv_bfloat16 h2 = __float2bfloat16(v.z), h3 = __float2bfloat16(v.w);
    __nv_bfloat16 l0 = __float2bfloat16(v.x - __bfloat162float(h0));
    __nv_bfloat16 l1 = __float2bfloat16(v.y - __bfloat162float(h1));
    __nv_bfloat16 l2 = __float2bfloat16(v.z - __bfloat162float(h2));
    __nv_bfloat16 l3 = __float2bfloat16(v.w - __bfloat162float(h3));
    hi[2 * i]     = __nv_bfloat162(h0, h1);
    hi[2 * i + 1] = __nv_bfloat162(h2, h3);
    lo[2 * i]     = __nv_bfloat162(l0, l1);
    lo[2 * i + 1] = __nv_bfloat162(l2, l3);
}

// ---------------------------------------------------------------------------
// proj_mma: C[m,n] = sum_k A[m,k]*B[n,k]  (NT, bf16x3 via HMMA, fp32 accum)
// Block tile 128(M)x64(N), K chunks of 32, 256 threads = 8 warps (4m x 2n),
// warp tile 32x32 = 2 m16 x 4 n8 fragments.
// mode 0: outf[m*DD+n]=(acc+bias[n])*scale   (O projection)
// mode 1: scatter fp32 to [B,H,S,DH]          (V)
// mode 2: scatter bf16 hi/lo to [B,H,S,DH]    (Q, K)
// ---------------------------------------------------------------------------
__global__ __launch_bounds__(256) void proj_mma(
    const __nv_bfloat16* __restrict__ Ah, const __nv_bfloat16* __restrict__ Al,
    const __nv_bfloat16* __restrict__ Bh, const __nv_bfloat16* __restrict__ Bl,
    const float* __restrict__ bias, float scale, int mode,
    float* __restrict__ outf, __nv_bfloat16* __restrict__ outh,
    __nv_bfloat16* __restrict__ outl)
{
    __shared__ __align__(16) __nv_bfloat16 sAh[128][STA], sAl[128][STA];
    __shared__ __align__(16) __nv_bfloat16 sBh[64][STA],  sBl[64][STA];

    const int tid  = threadIdx.x;
    const int lane = tid & 31, w = tid >> 5;
    const int wm = w >> 1, wn = w & 1;        // 4 x 2 warp grid
    const int grp = lane >> 2, qid = lane & 3;
    const int bm = blockIdx.y * 128;
    const int bn = blockIdx.x * 64;

    float c[2][4][4];
#pragma unroll
    for (int mi = 0; mi < 2; mi++)
#pragma unroll
        for (int ni = 0; ni < 4; ni++)
#pragma unroll
            for (int t = 0; t < 4; t++) c[mi][ni][t] = 0.0f;

    const int ar = tid >> 1, ac = (tid & 1) * 16;   // A loader: 128 rows x 2 thr
    const int br = tid >> 2, bc = (tid & 3) * 8;    // B loader: 64 rows x 4 thr

    for (int k0 = 0; k0 < DD; k0 += 32) {
        *(uint4*)&sAh[ar][ac]     = *(const uint4*)(Ah + (size_t)(bm + ar) * DD + k0 + ac);
        *(uint4*)&sAh[ar][ac + 8] = *(const uint4*)(Ah + (size_t)(bm + ar) * DD + k0 + ac + 8);
        *(uint4*)&sAl[ar][ac]     = *(const uint4*)(Al + (size_t)(bm + ar) * DD + k0 + ac);
        *(uint4*)&sAl[ar][ac + 8] = *(const uint4*)(Al + (size_t)(bm + ar) * DD + k0 + ac + 8);
        *(uint4*)&sBh[br][bc]     = *(const uint4*)(Bh + (size_t)(bn + br) * DD + k0 + bc);
        *(uint4*)&sBl[br][bc]     = *(const uint4*)(Bl + (size_t)(bn + br) * DD + k0 + bc);
        __syncthreads();

#pragma unroll
        for (int kk = 0; kk < 32; kk += 16) {
            uint32_t ra_h[2][4], ra_l[2][4];
#pragma unroll
            for (int mi = 0; mi < 2; mi++) {
                const int r0 = wm * 32 + mi * 16;
                ra_h[mi][0] = *(const uint32_t*)&sAh[r0 + grp][kk + qid * 2];
                ra_h[mi][1] = *(const uint32_t*)&sAh[r0 + grp + 8][kk + qid * 2];
                ra_h[mi][2] = *(const uint32_t*)&sAh[r0 + grp][kk + qid * 2 + 8];
                ra_h[mi][3] = *(const uint32_t*)&sAh[r0 + grp + 8][kk + qid * 2 + 8];
                ra_l[mi][0] = *(const uint32_t*)&sAl[r0 + grp][kk + qid * 2];
                ra_l[mi][1] = *(const uint32_t*)&sAl[r0 + grp + 8][kk + qid * 2];
                ra_l[mi][2] = *(const uint32_t*)&sAl[r0 + grp][kk + qid * 2 + 8];
                ra_l[mi][3] = *(const uint32_t*)&sAl[r0 + grp + 8][kk + qid * 2 + 8];
            }
#pragma unroll
            for (int ni = 0; ni < 4; ni++) {
                const int n0 = wn * 32 + ni * 8;
                uint32_t rb_h[2], rb_l[2];
                rb_h[0] = *(const uint32_t*)&sBh[n0 + grp][kk + qid * 2];
                rb_h[1] = *(const uint32_t*)&sBh[n0 + grp][kk + qid * 2 + 8];
                rb_l[0] = *(const uint32_t*)&sBl[n0 + grp][kk + qid * 2];
                rb_l[1] = *(const uint32_t*)&sBl[n0 + grp][kk + qid * 2 + 8];
#pragma unroll
                for (int mi = 0; mi < 2; mi++) {
                    mma16816(c[mi][ni], ra_h[mi], rb_h);
                    mma16816(c[mi][ni], ra_h[mi], rb_l);
                    mma16816(c[mi][ni], ra_l[mi], rb_h);
                }
            }
        }
        __syncthreads();
    }

    auto emit = [&](int m, int n, float acc) {
        const float v = (acc + bias[n]) * scale;
        if (mode == 0) {
            outf[(size_t)m * DD + n] = v;
        } else {
            const int b = m >> 10, s = m & 1023, h = n >> 6, d = n & 63;
            const size_t idx = ((size_t)((b * HH + h) * SS + s)) * DHD + d;
            if (mode == 1) {
                outf[idx] = v;
            } else {
                const __nv_bfloat16 hv = __float2bfloat16(v);
                outh[idx] = hv;
                outl[idx] = __float2bfloat16(v - __bfloat162float(hv));
            }
        }
    };

#pragma unroll
    for (int mi = 0; mi < 2; mi++)
#pragma unroll
        for (int ni = 0; ni < 4; ni++) {
            const int m0 = bm + wm * 32 + mi * 16 + grp;
            const int n0 = bn + wn * 32 + ni * 8 + qid * 2;
            emit(m0,     n0,     c[mi][ni][0]);
            emit(m0,     n0 + 1, c[mi][ni][1]);
            emit(m0 + 8, n0,     c[mi][ni][2]);
            emit(m0 + 8, n0 + 1, c[mi][ni][3]);
        }
}

// ---------------------------------------------------------------------------
// scores_mma: per (b,h) NT GEMM [1024x1024], K=64 (bf16x3 HMMA) + mask -> g_sc
// Block tile 128x64, grid (16, 8, 128).
// ---------------------------------------------------------------------------
__global__ __launch_bounds__(256) void scores_mma(
    const __nv_bfloat16* __restrict__ Qh, const __nv_bfloat16* __restrict__ Ql,
    const __nv_bfloat16* __restrict__ Kh, const __nv_bfloat16* __restrict__ Kl,
    const int* __restrict__ mask)
{
    __shared__ __align__(16) __nv_bfloat16 sAh[128][STA], sAl[128][STA];
    __shared__ __align__(16) __nv_bfloat16 sBh[64][STA],  sBl[64][STA];

    const int tid  = threadIdx.x;
    const int lane = tid & 31, w = tid >> 5;
    const int wm = w >> 1, wn = w & 1;
    const int grp = lane >> 2, qid = lane & 3;
    const int bh = blockIdx.z;
    const int b  = bh >> 4;
    const int bm = blockIdx.y * 128;
    const int bn = blockIdx.x * 64;
    const size_t qk = (size_t)bh * SS * DHD;

    float c[2][4][4];
#pragma unroll
    for (int mi = 0; mi < 2; mi++)
#pragma unroll
        for (int ni = 0; ni < 4; ni++)
#pragma unroll
            for (int t = 0; t < 4; t++) c[mi][ni][t] = 0.0f;

    const int ar = tid >> 1, ac = (tid & 1) * 16;
    const int br = tid >> 2, bc = (tid & 3) * 8;

    for (int k0 = 0; k0 < DHD; k0 += 32) {
        *(uint4*)&sAh[ar][ac]     = *(const uint4*)(Qh + qk + (size_t)(bm + ar) * DHD + k0 + ac);
        *(uint4*)&sAh[ar][ac + 8] = *(const uint4*)(Qh + qk + (size_t)(bm + ar) * DHD + k0 + ac + 8);
        *(uint4*)&sAl[ar][ac]     = *(const uint4*)(Ql + qk + (size_t)(bm + ar) * DHD + k0 + ac);
        *(uint4*)&sAl[ar][ac + 8] = *(const uint4*)(Ql + qk + (size_t)(bm + ar) * DHD + k0 + ac + 8);
        *(uint4*)&sBh[br][bc]     = *(const uint4*)(Kh + qk + (size_t)(bn + br) * DHD + k0 + bc);
        *(uint4*)&sBl[br][bc]     = *(const uint4*)(Kl + qk + (size_t)(bn + br) * DHD + k0 + bc);
        __syncthreads();

#pragma unroll
        for (int kk = 0; kk < 32; kk += 16) {
            uint32_t ra_h[2][4], ra_l[2][4];
#pragma unroll
            for (int mi = 0; mi < 2; mi++) {
                const int r0 = wm * 32 + mi * 16;
                ra_h[mi][0] = *(const uint32_t*)&sAh[r0 + grp][kk + qid * 2];
                ra_h[mi][1] = *(const uint32_t*)&sAh[r0 + grp + 8][kk + qid * 2];
                ra_h[mi][2] = *(const uint32_t*)&sAh[r0 + grp][kk + qid * 2 + 8];
                ra_h[mi][3] = *(const uint32_t*)&sAh[r0 + grp + 8][kk + qid * 2 + 8];
                ra_l[mi][0] = *(const uint32_t*)&sAl[r0 + grp][kk + qid * 2];
                ra_l[mi][1] = *(const uint32_t*)&sAl[r0 + grp + 8][kk + qid * 2];
                ra_l[mi][2] = *(const uint32_t*)&sAl[r0 + grp][kk + qid * 2 + 8];
                ra_l[mi][3] = *(const uint32_t*)&sAl[r0 + grp + 8][kk + qid * 2 + 8];
            }
#pragma unroll
            for (int ni = 0; ni < 4; ni++) {
                const int n0 = wn * 32 + ni * 8;
                uint32_t rb_h[2], rb_l[2];
                rb_h[0] = *(const uint32_t*)&sBh[n0 + grp][kk + qid * 2];
                rb_h[1] = *(const uint32_t*)&sBh[n0 + grp][kk + qid * 2 + 8];
                rb_l[0] = *(const uint32_t*)&sBl[n0 + grp][kk + qid * 2];
                rb_l[1] = *(const uint32_t*)&sBl[n0 + grp][kk + qid * 2 + 8];
#pragma unroll
                for (int mi = 0; mi < 2; mi++) {
                    mma16816(c[mi][ni], ra_h[mi], rb_h);
                    mma16816(c[mi][ni], ra_h[mi], rb_l);
                    mma16816(c[mi][ni], ra_l[mi], rb_h);
                }
            }
        }
        __syncthreads();
    }

    float* Sc = g_sc + (size_t)bh * SS * SS;
    const int* Mk = mask + (size_t)b * SS * SS;
    auto emit = [&](int m, int n, float acc) {
        Sc[(size_t)m * SS + n] = Mk[(size_t)m * SS + n] ? -1e18f : acc;
    };

#pragma unroll
    for (int mi = 0; mi < 2; mi++)
#pragma unroll
        for (int ni = 0; ni < 4; ni++) {
            const int m0 = bm + wm * 32 + mi * 16 + grp;
            const int n0 = bn + wn * 32 + ni * 8 + qid * 2;
            emit(m0,     n0,     c[mi][ni][0]);
            emit(m0,     n0 + 1, c[mi][ni][1]);
            emit(m0 + 8, n0,     c[mi][ni][2]);
            emit(m0 + 8, n0 + 1, c[mi][ni][3]);
        }
}

// ---------------------------------------------------------------------------
// softmax: per-row softmax + last-head graph reweighting
// ---------------------------------------------------------------------------
__device__ __forceinline__ float warp_max(float v) {
#pragma unroll
    for (int o = 16; o; o >>= 1) v = fmaxf(v, __shfl_xor_sync(0xffffffffu, v, o));
    return v;
}
__device__ __forceinline__ float warp_sum(float v) {
#pragma unroll
    for (int o = 16; o; o >>= 1) v += __shfl_xor_sync(0xffffffffu, v, o);
    return v;
}
__device__ __forceinline__ float block_max(float v, float* red) {
    const int lane = threadIdx.x & 31, wid = threadIdx.x >> 5;
    v = warp_max(v);
    if (lane == 0) red[wid] = v;
    __syncthreads();
    if (wid == 0) {
        float z = (lane < 8) ? red[lane] : -3.4e38f;
        z = warp_max(z);
        if (lane == 0) red[8] = z;
    }
    __syncthreads();
    const float r = red[8];
    __syncthreads();
    return r;
}
__device__ __forceinline__ float block_sum(float v, float* red) {
    const int lane = threadIdx.x & 31, wid = threadIdx.x >> 5;
    v = warp_sum(v);
    if (lane == 0) red[wid] = v;
    __syncthreads();
    if (wid == 0) {
        float z = (lane < 8) ? red[lane] : 0.0f;
        z = warp_sum(z);
        if (lane == 0) red[8] = z;
    }
    __syncthreads();
    const float r = red[8];
    __syncthreads();
    return r;
}

__global__ __launch_bounds__(256) void softmax_kernel(const float* __restrict__ graph)
{
    __shared__ float red[9];
    const int row = blockIdx.x;
    const int bh = row >> 10;
    const int m  = row & 1023;
    const int b  = bh >> 4;
    const int h  = bh & 15;
    float* Sc = g_sc + (size_t)row * SS;
    const int t = threadIdx.x;

    float x0 = Sc[t], x1 = Sc[t + 256], x2 = Sc[t + 512], x3 = Sc[t + 768];
    const float mx = block_max(fmaxf(fmaxf(x0, x1), fmaxf(x2, x3)), red);

    float e0 = __expf(x0 - mx), e1 = __expf(x1 - mx);
    float e2 = __expf(x2 - mx), e3 = __expf(x3 - mx);
    const float Z = block_sum(e0 + e1 + e2 + e3, red);
    const float inv = 1.0f / Z;
    float p0 = e0 * inv, p1 = e1 * inv, p2 = e2 * inv, p3 = e3 * inv;

    if (h == HH - 1) {
        const float* g = graph + (size_t)b * SS * SS + (size_t)m * SS;
        const float w0 = p0 * g[t],       w1 = p1 * g[t + 256];
        const float w2 = p2 * g[t + 512], w3 = p3 * g[t + 768];
        const float sw = block_sum(w0 + w1 + w2 + w3, red);
        const float invw = 1.0f / (sw + 1e-9f);
        p0 = w0 * invw; p1 = w1 * invw; p2 = w2 * invw; p3 = w3 * invw;
    }
    Sc[t] = p0; Sc[t + 256] = p1; Sc[t + 512] = p2; Sc[t + 768] = p3;
}

// ---------------------------------------------------------------------------
// ctx = attn @ V (SIMT NN GEMM) -> g_ctx [B,S,D]
// ---------------------------------------------------------------------------
__global__ __launch_bounds__(256) void ctx_kernel()
{
    const int bh = blockIdx.y;
    const int b = bh >> 4;
    const int h = bh & 15;
    const int bm = blockIdx.x * 128;
    const float* A = g_sc + (size_t)bh * SS * SS;
    const float* V = g_v  + (size_t)bh * SS * DHD;

    __shared__ float As[8][128];
    __shared__ float Bs[8][64];
    const int tid = threadIdx.x;
    const int tm = tid >> 4;
    const int tn = tid & 15;
    const int lr = tid >> 1;
    const int lc = (tid & 1) * 4;

    float acc[8][4];
#pragma unroll
    for (int i = 0; i < 8; i++)
#pragma unroll
        for (int j = 0; j < 4; j++) acc[i][j] = 0.0f;

    for (int k0 = 0; k0 < SS; k0 += 8) {
        float4 av = *(const float4*)(A + (size_t)(bm + lr) * SS + k0 + lc);
        As[lc + 0][lr] = av.x; As[lc + 1][lr] = av.y;
        As[lc + 2][lr] = av.z; As[lc + 3][lr] = av.w;
        if (tid < 128) {
            const int r = tid >> 4;
            const int c = (tid & 15) * 4;
            *(float4*)&Bs[r][c] = *(const float4*)(V + (size_t)(k0 + r) * DHD + c);
        }
        __syncthreads();
#pragma unroll
        for (int kk = 0; kk < 8; kk++) {
            float a[8], bfr[4];
            *(float4*)(a)     = *(const float4*)&As[kk][tm * 8];
            *(float4*)(a + 4) = *(const float4*)&As[kk][tm * 8 + 4];
            *(float4*)(bfr)   = *(const float4*)&Bs[kk][tn * 4];
#pragma unroll
            for (int i = 0; i < 8; i++)
#pragma unroll
                for (int j = 0; j < 4; j++) acc[i][j] += a[i] * bfr[j];
        }
        __syncthreads();
    }

#pragma unroll
    for (int i = 0; i < 8; i++) {
        const int m = bm + tm * 8 + i;
#pragma unroll
        for (int j = 0; j < 4; j++) {
            const int n = tn * 4 + j;
            g_ctx[((size_t)(b * SS + m)) * DD + h * DHD + n] = acc[i][j];
        }
    }
}

// ---------------------------------------------------------------------------
// Launch
// ---------------------------------------------------------------------------
extern "C" void kernel_launch(void* const* d_in, const int* in_sizes, int n_in,
                              void* d_out, int out_size)
{
    const float* key   = (const float*)d_in[0];
    const float* value = (const float*)d_in[1];
    const float* query = (const float*)d_in[2];
    const int*   mask  = (const int*)d_in[3];
    const float* graph = (const float*)d_in[4];
    const float* Wq = (const float*)d_in[5];  const float* bq = (const float*)d_in[6];
    const float* Wk = (const float*)d_in[7];  const float* bk = (const float*)d_in[8];
    const float* Wv = (const float*)d_in[9];  const float* bv = (const float*)d_in[10];
    const float* Wo = (const float*)d_in[11]; const float* bo = (const float*)d_in[12];
    float* out = (float*)d_out;

    __nv_bfloat16 *xh, *xl, *wh, *wl, *qh, *ql, *kh, *kl;
    float *vb, *ctxb;
    cudaGetSymbolAddress((void**)&xh, g_xh);  cudaGetSymbolAddress((void**)&xl, g_xl);
    cudaGetSymbolAddress((void**)&wh, g_wh);  cudaGetSymbolAddress((void**)&wl, g_wl);
    cudaGetSymbolAddress((void**)&qh, g_qh);  cudaGetSymbolAddress((void**)&ql, g_ql);
    cudaGetSymbolAddress((void**)&kh, g_kh);  cudaGetSymbolAddress((void**)&kl, g_kl);
    cudaGetSymbolAddress((void**)&vb, g_v);   cudaGetSymbolAddress((void**)&ctxb, g_ctx);

    const int n4x = MROWS * DD / 4;
    const int n4w = DD * DD / 4;
    const dim3 projGrid(DD / 64, MROWS / 128);   // (16, 64)

    // Q projection -> bf16 hi/lo scatter (scale 1/sqrt(64) applied in epilogue)
    split_kernel<<<(n4w + 255) / 256, 256>>>((const float4*)Wq, (__nv_bfloat162*)wh, (__nv_bfloat162*)wl, n4w);
    split_kernel<<<(n4x + 255) / 256, 256>>>((const float4*)query, (__nv_bfloat162*)xh, (__nv_bfloat162*)xl, n4x);
    proj_mma<<<projGrid, 256>>>(xh, xl, wh, wl, bq, 0.125f, 2, nullptr, qh, ql);

    // K projection -> bf16 hi/lo scatter
    split_kernel<<<(n4w + 255) / 256, 256>>>((const float4*)Wk, (__nv_bfloat162*)wh, (__nv_bfloat162*)wl, n4w);
    split_kernel<<<(n4x + 255) / 256, 256>>>((const float4*)key, (__nv_bfloat162*)xh, (__nv_bfloat162*)xl, n4x);
    proj_mma<<<projGrid, 256>>>(xh, xl, wh, wl, bk, 1.0f, 2, nullptr, kh, kl);

    // V projection -> fp32 scatter
    split_kernel<<<(n4w + 255) / 256, 256>>>((const float4*)Wv, (__nv_bfloat162*)wh, (__nv_bfloat162*)wl, n4w);
    split_kernel<<<(n4x + 255) / 256, 256>>>((const float4*)value, (__nv_bfloat162*)xh, (__nv_bfloat162*)xl, n4x);
    proj_mma<<<projGrid, 256>>>(xh, xl, wh, wl, bv, 1.0f, 1, vb, nullptr, nullptr);

    // scores + mask (HMMA), softmax, ctx
    dim3 scGrid(SS / 64, SS / 128, BB * HH);     // (16, 8, 128)
    scores_mma<<<scGrid, 256>>>(qh, ql, kh, kl, mask);

    softmax_kernel<<<BB * HH * SS, 256>>>(graph);

    dim3 ctxGrid(SS / 128, BB * HH);             // (8, 128)
    ctx_kernel<<<ctxGrid, 256>>>();

    // Output projection (HMMA) -> d_out
    split_kernel<<<(n4w + 255) / 256, 256>>>((const float4*)Wo, (__nv_bfloat162*)wh, (__nv_bfloat162*)wl, n4w);
    split_kernel<<<(n4x + 255) / 256, 256>>>((const float4*)ctxb, (__nv_bfloat162*)xh, (__nv_bfloat162*)xl, n4x);
    proj_mma<<<projGrid, 256>>>(xh, xl, wh, wl, bo, 1.0f, 0, out, nullptr, nullptr);
}